// round 15
// baseline (speedup 1.0000x reference)
#include <cuda_runtime.h>
#include <math.h>

// Problem dims: y_true/y_pred shape (1,1,160,192,160) fp32
#define DD 160
#define HH 192
#define WW 160
#define W4 (WW/4)               // 40 float4 per row
#define VOL (DD*HH*WW)          // 4,915,200
#define VOL4 (VOL/4)
#define RAD 4                   // box window radius (win=9)
#define WIN 9
#define WSIZE 729.0f
#define INV_WSIZE (1.0f/729.0f)
#define NCH 15                  // 3 pairs x 5 channels (A,B,A2,B2,AB)
#define HCHB 48                 // output h-rows per fusedwh block (4 chunks)
#define DCH2 40                 // d-planes per pass_d thread (4 chunks)

#define RING_BYTES (WIN * NCH * WW * 4)   // 86,400 B dynamic smem

// ---------------- scratch (device globals: no allocation allowed) ----------
__device__ float g_s1[(size_t)NCH * VOL];   // h∘w-boxed product channels
__device__ double g_acc[3];                 // per-pair sum of cc

// ---------------- small float4 helpers --------------------------------------
__device__ __forceinline__ float4 f4add(float4 a, float4 b) {
    return make_float4(a.x+b.x, a.y+b.y, a.z+b.z, a.w+b.w);
}
__device__ __forceinline__ float4 f4sub(float4 a, float4 b) {
    return make_float4(a.x-b.x, a.y-b.y, a.z-b.z, a.w-b.w);
}

// ---------------- accumulator reset ----------------------------------------
__global__ void k_zero_acc() {
    if (threadIdx.x < 3) g_acc[threadIdx.x] = 0.0;
}

// ---------------- 3x3x3 stencils on h-slot ring smem ------------------------
__device__ __forceinline__ void stencil_rows(const float sm[3][3][WW + 2],
                                             int y0, int y1, int y2, int cw,
                                             float& lap, float& shp) {
    int ys[3] = {y0, y1, y2};
    const float m3[3] = {1.f, 2.f, 1.f};
    float c = sm[y1][1][cw];
    lap = 6.f * c
        - sm[y1][1][cw - 1] - sm[y1][1][cw + 1]
        - sm[y0][1][cw]     - sm[y2][1][cw]
        - sm[y1][0][cw]     - sm[y1][2][cw];

    float gx = 0.f, gy = 0.f, gz = 0.f;
    #pragma unroll
    for (int dz = 0; dz < 3; dz++)
        #pragma unroll
        for (int dy = 0; dy < 3; dy++)
            gx += m3[dy] * (sm[ys[dy]][dz][cw + 1] - sm[ys[dy]][dz][cw - 1]);
    #pragma unroll
    for (int dy = 0; dy < 3; dy++)
        #pragma unroll
        for (int dw = 0; dw < 3; dw++)
            gy += m3[dw] * (sm[ys[dy]][2][cw + dw - 1] - sm[ys[dy]][0][cw + dw - 1]);
    #pragma unroll
    for (int dz = 0; dz < 3; dz++)
        #pragma unroll
        for (int dw = 0; dw < 3; dw++)
            gz += m3[dz] * (sm[y2][dz][cw + dw - 1] - sm[y0][dz][cw + dw - 1]);

    shp = sqrtf(gx * gx + gy * gy + gz * gz);
}

// load input row r (3 d-planes x 2 vols) into h-slot ring
__device__ __forceinline__ void load_row(float (*sA)[3][WW + 2],
                                         float (*sB)[3][WW + 2],
                                         const float* __restrict__ I,
                                         const float* __restrict__ J,
                                         int d, int r, int t) {
    int slot = (r + 9) % 3;
    #pragma unroll
    for (int dz = 0; dz < 3; dz++) {
        int dd = d + dz - 1;
        bool rok = (dd >= 0 && dd < DD && r >= 0 && r < HH);
        size_t rb = ((size_t)dd * HH + r) * WW;
        #pragma unroll
        for (int ii = 0; ii < 2; ii++) {
            int idx = t + ii * WW;
            if (idx < WW + 2) {
                int w = idx - 1;
                float vi = 0.f, vj = 0.f;
                if (rok && w >= 0 && w < WW) {
                    vi = __ldg(I + rb + w);
                    vj = __ldg(J + rb + w);
                }
                sA[slot][dz][idx] = vi;
                sB[slot][dz][idx] = vj;
            }
        }
    }
}

// ---------------- fused: deriv + products + w-box + sliding h-box -----------
// block = (d, h-chunk), 160 threads, marches h. The 9-deep h-box ring lives
// in SHARED memory (per-thread column [slot][c][t]) — zero local-mem spill.
// Window-9 slide: incoming row r and outgoing row r-9 share slot r%9.
__global__ __launch_bounds__(WW) void k_fusedwh(const float* __restrict__ I,
                                                const float* __restrict__ J) {
    __shared__ float sA[3][3][WW + 2];
    __shared__ float sB[3][3][WW + 2];
    __shared__ float vals[6][WW + 8];
    extern __shared__ float ring[];        // [WIN][NCH][WW]
    const int d  = blockIdx.x;
    const int h0 = blockIdx.y * HCHB;
    const int t  = threadIdx.x;

    if (t < 4) {
        #pragma unroll
        for (int c = 0; c < 6; c++) {
            vals[c][t] = 0.f;
            vals[c][WW + 4 + t] = 0.f;
        }
    }

    float S[NCH];
    #pragma unroll
    for (int c = 0; c < NCH; c++) S[c] = 0.f;

    const int s_begin = h0 - 2 * RAD;
    load_row(sA, sB, I, J, d, s_begin + 3, t);
    load_row(sA, sB, I, J, d, s_begin + 4, t);
    __syncthreads();

    // slot of the incoming row r = s+4 ; wraps 0..8
    int slot = ((s_begin + RAD) % WIN + WIN) % WIN;

    #pragma unroll 1
    for (int s = s_begin; s < h0 + HCHB; s++) {
        load_row(sA, sB, I, J, d, s + 5, t);
        __syncthreads();

        const int r = s + RAD;                 // incoming product row
        const int q = r - WIN;                 // outgoing row (same slot)
        const bool addok  = (r >= 0 && r < HH);
        const bool dropok = (q >= 0 && q >= h0 - RAD);

        if (addok) {
            int y0 = (r - 1 + 9) % 3, y1 = (r + 9) % 3, y2 = (r + 1 + 9) % 3;
            float lapI, shpI, lapJ, shpJ;
            stencil_rows(sA, y0, y1, y2, t + 1, lapI, shpI);
            stencil_rows(sB, y0, y1, y2, t + 1, lapJ, shpJ);
            vals[0][t + 4] = sA[y1][1][t + 1];
            vals[1][t + 4] = sB[y1][1][t + 1];
            vals[2][t + 4] = lapI;
            vals[3][t + 4] = lapJ;
            vals[4][t + 4] = shpI;
            vals[5][t + 4] = shpJ;
        }
        __syncthreads();

        float* rs = ring + (size_t)slot * NCH * WW + t;

        if (addok) {
            float hb[NCH];
            #pragma unroll
            for (int c = 0; c < NCH; c++) hb[c] = 0.f;
            #pragma unroll
            for (int dx = -RAD; dx <= RAD; dx++) {
                int x = t + 4 + dx;            // zero-padded, always in-range
                float a0 = vals[0][x], b0 = vals[1][x];
                float a1 = vals[2][x], b1 = vals[3][x];
                float a2 = vals[4][x], b2 = vals[5][x];
                hb[0] += a0;       hb[1] += b0;
                hb[2] += a0 * a0;  hb[3] += b0 * b0;  hb[4]  += a0 * b0;
                hb[5] += a1;       hb[6] += b1;
                hb[7] += a1 * a1;  hb[8] += b1 * b1;  hb[9]  += a1 * b1;
                hb[10] += a2;      hb[11] += b2;
                hb[12] += a2 * a2; hb[13] += b2 * b2; hb[14] += a2 * b2;
            }
            // read old (row q) BEFORE overwriting the shared slot
            #pragma unroll
            for (int c = 0; c < NCH; c++) {
                float old = dropok ? rs[c * WW] : 0.f;
                rs[c * WW] = hb[c];
                S[c] += hb[c] - old;
            }
        } else if (dropok) {
            #pragma unroll
            for (int c = 0; c < NCH; c++)
                S[c] -= rs[c * WW];
        }

        if (s >= h0) {
            size_t idx = ((size_t)d * HH + s) * WW + t;
            #pragma unroll
            for (int c = 0; c < NCH; c++)
                g_s1[(size_t)c * VOL + idx] = S[c];
        }

        slot++;
        if (slot == WIN) slot = 0;
    }
}

// ---------------- NCC formula ----------------------------------------------
__device__ __forceinline__ float ncc_cc(float Is, float Js, float I2s,
                                        float J2s, float IJs) {
    float uI = Is * INV_WSIZE;
    float uJ = Js * INV_WSIZE;
    float cross = IJs - uJ * Is - uI * Js + uI * uJ * WSIZE;
    float Iv = I2s - 2.f * uI * Is + uI * uI * WSIZE;
    float Jv = J2s - 2.f * uJ * Js + uJ * uJ * WSIZE;
    return cross * cross / (Iv * Jv + 1e-5f);
}

// ---------------- pass: sliding d-box + NCC, ring-free ----------------------
// Outgoing plane is RE-READ from global (8 steps stale -> guaranteed L2 hit:
// reuse window = 92160 thr * 8 steps * 80B = 59MB < 126MB L2). No local ring.
// threads = 3 * 4 * HH * W4 = 92160 -> 720 blocks x 128
__global__ __launch_bounds__(128) void k_pass_d() {
    int tid = blockIdx.x * 128 + threadIdx.x;
    int w4 = tid % W4;  tid /= W4;
    int h  = tid % HH;  tid /= HH;
    int dc = tid % 4;   tid /= 4;
    int pair = tid;
    if (pair >= 3) return;

    const float4* __restrict__ ch[5];
    #pragma unroll
    for (int c = 0; c < 5; c++)
        ch[c] = (const float4*)g_s1 + (size_t)(pair * 5 + c) * VOL4;

    const int poff = h * W4 + w4;
    const int pstride = HH * W4;
    const float4 z4 = make_float4(0.f, 0.f, 0.f, 0.f);

    float4 S[5];
    #pragma unroll
    for (int c = 0; c < 5; c++) S[c] = z4;

    const int d0 = dc * DCH2;

    // warmup: planes [d0-4, d0+4)
    for (int dd = d0 - RAD; dd < d0 + RAD; dd++) {
        if (dd < 0 || dd >= DD) continue;
        #pragma unroll
        for (int c = 0; c < 5; c++)
            S[c] = f4add(S[c], __ldg(ch[c] + dd * pstride + poff));
    }

    double local = 0.0;
    #pragma unroll 2
    for (int d = d0; d < d0 + DCH2; d++) {
        const int dp = d + RAD, dm = d - RAD;
        float4 nv[5], ov[5];
        #pragma unroll
        for (int c = 0; c < 5; c++)
            nv[c] = (dp < DD) ? __ldg(ch[c] + dp * pstride + poff) : z4;
        #pragma unroll
        for (int c = 0; c < 5; c++)
            ov[c] = (dm >= 0) ? __ldg(ch[c] + dm * pstride + poff) : z4;

        #pragma unroll
        for (int c = 0; c < 5; c++) S[c] = f4add(S[c], nv[c]);

        float cx = ncc_cc(S[0].x, S[1].x, S[2].x, S[3].x, S[4].x);
        float cy = ncc_cc(S[0].y, S[1].y, S[2].y, S[3].y, S[4].y);
        float cz = ncc_cc(S[0].z, S[1].z, S[2].z, S[3].z, S[4].z);
        float cw = ncc_cc(S[0].w, S[1].w, S[2].w, S[3].w, S[4].w);
        local += (double)((cx + cy) + (cz + cw));

        #pragma unroll
        for (int c = 0; c < 5; c++) S[c] = f4sub(S[c], ov[c]);
    }

    // warp + block reduce, one atomic per block (block is single-pair)
    unsigned mask = 0xFFFFFFFFu;
    #pragma unroll
    for (int off = 16; off > 0; off >>= 1)
        local += __shfl_down_sync(mask, local, off);

    __shared__ double red[4];
    int lane = threadIdx.x & 31, warp = threadIdx.x >> 5;
    if (lane == 0) red[warp] = local;
    __syncthreads();
    if (threadIdx.x == 0) {
        double tsum = red[0] + red[1] + red[2] + red[3];
        atomicAdd(&g_acc[pair], tsum);
    }
}

// ---------------- final combine ---------------------------------------------
__global__ void k_final(float* out) {
    double m = (0.8 * g_acc[0] + 0.1 * g_acc[1] + 0.1 * g_acc[2]) / (double)VOL;
    out[0] = (float)(-m);
}

// ---------------- launch ----------------------------------------------------
extern "C" void kernel_launch(void* const* d_in, const int* in_sizes, int n_in,
                              void* d_out, int out_size) {
    const float* I = (const float*)d_in[0];  // y_true
    const float* J = (const float*)d_in[1];  // y_pred
    float* out = (float*)d_out;

    static int attr_done = 0;
    if (!attr_done) {
        cudaFuncSetAttribute(k_fusedwh,
                             cudaFuncAttributeMaxDynamicSharedMemorySize,
                             RING_BYTES);
        attr_done = 1;
    }

    k_zero_acc<<<1, 32>>>();

    dim3 gridF(DD, HH / HCHB);                       // 160 x 4 = 640 blocks
    k_fusedwh<<<gridF, WW, RING_BYTES>>>(I, J);

    int nthreads_d = 3 * 4 * HH * W4;                // 92160
    k_pass_d<<<nthreads_d / 128, 128>>>();

    k_final<<<1, 1>>>(out);
}